// round 6
// baseline (speedup 1.0000x reference)
#include <cuda_runtime.h>
#include <cstdint>

#define D 128
#define MAXN 100000

// Scratch for aggregated features X' = segment_sum(gather(X))
__device__ float g_Xp[(size_t)MAXN * D];

typedef unsigned long long ull_t;

// ---- Blackwell packed f32x2 helpers ----
__device__ __forceinline__ ull_t pack2(float lo, float hi) {
    ull_t r;
    asm("mov.b64 %0, {%1,%2};" : "=l"(r) : "f"(lo), "f"(hi));
    return r;
}
__device__ __forceinline__ void unpack2(ull_t v, float& lo, float& hi) {
    asm("mov.b64 {%0,%1}, %2;" : "=f"(lo), "=f"(hi) : "l"(v));
}
__device__ __forceinline__ void fma2(ull_t& d, ull_t a, ull_t b) {
    asm("fma.rn.f32x2 %0, %1, %2, %0;" : "+l"(d) : "l"(a), "l"(b));
}

// ============================================================================
// Kernel 1: row aggregation. One warp per destination row; each lane owns 4
// consecutive features (float4) so one warp-load fetches a full 512B X row.
// No smem -> high occupancy -> enough MLP to saturate L2.  (measured ~53us)
// ============================================================================
__global__ void __launch_bounds__(256)
agg_kernel(const float4* __restrict__ X4,
           const int* __restrict__ rowptr,
           const int* __restrict__ colidx,
           float4* __restrict__ Xp4,
           int n) {
    const int w    = (blockIdx.x * blockDim.x + threadIdx.x) >> 5;
    const int lane = threadIdx.x & 31;
    if (w >= n) return;

    int e        = rowptr[w];
    const int e1 = rowptr[w + 1];
    float4 acc = make_float4(0.f, 0.f, 0.f, 0.f);

    for (; e + 8 <= e1; e += 8) {
        float4 v[8];
#pragma unroll
        for (int i = 0; i < 8; i++)
            v[i] = X4[(size_t)colidx[e + i] * 32 + lane];
#pragma unroll
        for (int i = 0; i < 8; i++) {
            acc.x += v[i].x; acc.y += v[i].y;
            acc.z += v[i].z; acc.w += v[i].w;
        }
    }
    for (; e < e1; e++) {
        float4 v = X4[(size_t)colidx[e] * 32 + lane];
        acc.x += v.x; acc.y += v.y; acc.z += v.z; acc.w += v.w;
    }
    Xp4[(size_t)w * 32 + lane] = acc;
}

// ============================================================================
// Kernel 2: dense GEMM  out[n,128] = X'[n,128] @ W[128,128]  via packed f32x2.
// 512 threads, 256-row x 128-col block tile, thread tile 8x8.
// Same smem (192KB, 1 block/SM) but 16 warps/SM (4/SMSP) to hide LDS latency
// -- R5 was latency-bound at 2 warps/SMSP (fma 49.5%, issue 41.5%).
// Per warp per 2k: 8 broadcast LDS.64 (aa) + 4 LDS.128 (bb) = 16 wavefronts
// vs 64 fma2 -> fma-pipe bound.
// ============================================================================
#define GT 512
#define GROWS 256
#define GEMM_SMEM (D * D * 4 + GROWS * D * 4)

__global__ void __launch_bounds__(GT, 1)
gemm_kernel(const float* __restrict__ Xp,
            const float* __restrict__ W,
            float* __restrict__ out,
            int n) {
    extern __shared__ float smem[];
    float* sW = smem;          // [128][128]
    float* sX = smem + D * D;  // [256][128]

    const int tid  = threadIdx.x;
    const int row0 = blockIdx.x * GROWS;

    // Load W (vectorized)
    {
        const float4* W4  = reinterpret_cast<const float4*>(W);
        float4*       sW4 = reinterpret_cast<float4*>(sW);
#pragma unroll
        for (int i = tid; i < (D * D) / 4; i += GT) sW4[i] = W4[i];
    }

    // Load X' tile (vectorized, zero-fill past n)
    {
        const float4* Xp4 = reinterpret_cast<const float4*>(Xp);
        float4*       sX4 = reinterpret_cast<float4*>(sX);
#pragma unroll
        for (int i = tid; i < GROWS * (D / 4); i += GT) {
            const int row = i >> 5;  // i / 32
            const int gr  = row0 + row;
            float4 v = make_float4(0.f, 0.f, 0.f, 0.f);
            if (gr < n) v = Xp4[(size_t)gr * 32 + (i & 31)];
            sX4[i] = v;
        }
    }
    __syncthreads();

    const int ri = tid >> 4;  // 0..31 : rows ri*8 .. ri*8+7
    const int ci = tid & 15;  // 0..15 : cols ci*8 .. ci*8+7

    ull_t acc[8][4];
#pragma unroll
    for (int j = 0; j < 8; j++)
#pragma unroll
        for (int c = 0; c < 4; c++) acc[j][c] = 0ULL;

    const ulonglong2* sW2v = reinterpret_cast<const ulonglong2*>(sW);
    // ull2 index of &sW[k*128 + ci*8] = k*32 + ci*2

#pragma unroll 1
    for (int k0 = 0; k0 < D; k0 += 2) {
        const ulonglong2 b0a = sW2v[k0 * 32 + ci * 2];
        const ulonglong2 b0b = sW2v[k0 * 32 + ci * 2 + 1];
        const ulonglong2 b1a = sW2v[(k0 + 1) * 32 + ci * 2];
        const ulonglong2 b1b = sW2v[(k0 + 1) * 32 + ci * 2 + 1];
#pragma unroll
        for (int j = 0; j < 8; j++) {
            const float2 a2 =
                *reinterpret_cast<const float2*>(&sX[(ri * 8 + j) * D + k0]);
            const ull_t pa0 = pack2(a2.x, a2.x);
            const ull_t pa1 = pack2(a2.y, a2.y);
            fma2(acc[j][0], pa0, b0a.x);
            fma2(acc[j][1], pa0, b0a.y);
            fma2(acc[j][2], pa0, b0b.x);
            fma2(acc[j][3], pa0, b0b.y);
            fma2(acc[j][0], pa1, b1a.x);
            fma2(acc[j][1], pa1, b1a.y);
            fma2(acc[j][2], pa1, b1b.x);
            fma2(acc[j][3], pa1, b1b.y);
        }
    }

    // Store 8 rows x 8 cols per thread
#pragma unroll
    for (int j = 0; j < 8; j++) {
        const int row = row0 + ri * 8 + j;
        if (row >= n) continue;
        float lo0, hi0, lo1, hi1, lo2, hi2, lo3, hi3;
        unpack2(acc[j][0], lo0, hi0);
        unpack2(acc[j][1], lo1, hi1);
        unpack2(acc[j][2], lo2, hi2);
        unpack2(acc[j][3], lo3, hi3);
        float4* o = reinterpret_cast<float4*>(&out[(size_t)row * D + ci * 8]);
        o[0] = make_float4(lo0, hi0, lo1, hi1);
        o[1] = make_float4(lo2, hi2, lo3, hi3);
    }
}

extern "C" void kernel_launch(void* const* d_in, const int* in_sizes, int n_in,
                              void* d_out, int out_size) {
    const float* X      = (const float*)d_in[0];
    const float* W      = (const float*)d_in[1];
    const int*   rowptr = (const int*)d_in[2];
    const int*   colidx = (const int*)d_in[3];
    float*       out    = (float*)d_out;

    const int n = in_sizes[2] - 1;  // row_pointers has N+1 entries

    float* Xp;
    cudaGetSymbolAddress((void**)&Xp, g_Xp);

    // Kernel 1: aggregation (one warp per row)
    {
        const int total_threads = n * 32;
        const int grid = (total_threads + 255) / 256;
        agg_kernel<<<grid, 256>>>((const float4*)X, rowptr, colidx,
                                  (float4*)Xp, n);
    }

    // Kernel 2: GEMM
    {
        cudaFuncSetAttribute(gemm_kernel,
                             cudaFuncAttributeMaxDynamicSharedMemorySize,
                             GEMM_SMEM);
        const int grid = (n + GROWS - 1) / GROWS;
        gemm_kernel<<<grid, GT, GEMM_SMEM>>>(Xp, W, out, n);
    }
}

// round 8
// speedup vs baseline: 1.5529x; 1.5529x over previous
#include <cuda_runtime.h>
#include <cuda_bf16.h>
#include <cstdint>

#define D 128
#define MAXN 100000

// ---- global scratch: X' split into bf16 hi/lo, W transposed split ----
__device__ uint4 g_XpHi4[(size_t)MAXN * 16];  // [row][128 bf16] = 256B/row
__device__ uint4 g_XpLo4[(size_t)MAXN * 16];
__device__ uint4 g_WtHi4[D * D / 8];          // [n][k] bf16, 256B/row
__device__ uint4 g_WtLo4[D * D / 8];

// ---- helpers ----
__device__ __forceinline__ void split2(float a, float b, unsigned& hi, unsigned& lo) {
    __nv_bfloat16 ha = __float2bfloat16_rn(a);
    __nv_bfloat16 hb = __float2bfloat16_rn(b);
    float ra = a - __bfloat162float(ha);
    float rb = b - __bfloat162float(hb);
    __nv_bfloat162 hv; hv.x = ha; hv.y = hb;
    __nv_bfloat162 lv = __floats2bfloat162_rn(ra, rb);
    hi = *reinterpret_cast<unsigned*>(&hv);
    lo = *reinterpret_cast<unsigned*>(&lv);
}

__device__ __forceinline__ unsigned smem_u32(const void* p) {
    unsigned a;
    asm("{ .reg .u64 t; cvta.to.shared.u64 t, %1; cvt.u32.u64 %0, t; }"
        : "=r"(a) : "l"(p));
    return a;
}

#define STS128(addr, v)                                                     \
    asm volatile("st.shared.v4.b32 [%0], {%1,%2,%3,%4};" ::"r"(addr),       \
                 "r"((v).x), "r"((v).y), "r"((v).z), "r"((v).w) : "memory")

#define LDSM4(r0, r1, r2, r3, addr)                                         \
    asm volatile("ldmatrix.sync.aligned.m8n8.x4.shared.b16 "                \
                 "{%0,%1,%2,%3}, [%4];"                                     \
                 : "=r"(r0), "=r"(r1), "=r"(r2), "=r"(r3) : "r"(addr))

#define MMA16816(d, a, b0, b1)                                              \
    asm volatile("mma.sync.aligned.m16n8k16.row.col.f32.bf16.bf16.f32 "     \
                 "{%0,%1,%2,%3}, {%4,%5,%6,%7}, {%8,%9}, {%0,%1,%2,%3};"    \
                 : "+f"((d)[0]), "+f"((d)[1]), "+f"((d)[2]), "+f"((d)[3])   \
                 : "r"((a)[0]), "r"((a)[1]), "r"((a)[2]), "r"((a)[3]),      \
                   "r"(b0), "r"(b1))

// swizzled byte offset inside a 256B-pitch bf16 tile
__device__ __forceinline__ unsigned sw_off(int row, int chunk) {
    return (unsigned)(row * 256 + ((chunk ^ (row & 7)) << 4));
}

// ============================================================================
// Kernel 0: W[128][128] fp32 -> transposed bf16 hi/lo  Wt[n][k]
// ============================================================================
__global__ void wconv_kernel(const float* __restrict__ W) {
    const int idx = blockIdx.x * blockDim.x + threadIdx.x;
    if (idx >= D * D) return;
    const int nrow = idx >> 7;
    const int k    = idx & 127;
    const float w = W[k * D + nrow];
    __nv_bfloat16 hi = __float2bfloat16_rn(w);
    __nv_bfloat16 lo = __float2bfloat16_rn(w - __bfloat162float(hi));
    reinterpret_cast<__nv_bfloat16*>(g_WtHi4)[nrow * D + k] = hi;
    reinterpret_cast<__nv_bfloat16*>(g_WtLo4)[nrow * D + k] = lo;
}

// ============================================================================
// Kernel 1: row aggregation -> bf16 hi/lo split output (one warp per row).
// ============================================================================
__global__ void __launch_bounds__(256)
agg_kernel(const float4* __restrict__ X4,
           const int* __restrict__ rowptr,
           const int* __restrict__ colidx,
           int n) {
    const int w    = (blockIdx.x * blockDim.x + threadIdx.x) >> 5;
    const int lane = threadIdx.x & 31;
    if (w >= n) return;

    int e        = rowptr[w];
    const int e1 = rowptr[w + 1];
    float4 acc = make_float4(0.f, 0.f, 0.f, 0.f);

    for (; e + 8 <= e1; e += 8) {
        float4 v[8];
#pragma unroll
        for (int i = 0; i < 8; i++)
            v[i] = X4[(size_t)colidx[e + i] * 32 + lane];
#pragma unroll
        for (int i = 0; i < 8; i++) {
            acc.x += v[i].x; acc.y += v[i].y;
            acc.z += v[i].z; acc.w += v[i].w;
        }
    }
    for (; e < e1; e++) {
        float4 v = X4[(size_t)colidx[e] * 32 + lane];
        acc.x += v.x; acc.y += v.y; acc.z += v.z; acc.w += v.w;
    }

    unsigned h0, l0, h1, l1;
    split2(acc.x, acc.y, h0, l0);
    split2(acc.z, acc.w, h1, l1);
    reinterpret_cast<uint2*>(g_XpHi4)[(size_t)w * 32 + lane] = make_uint2(h0, h1);
    reinterpret_cast<uint2*>(g_XpLo4)[(size_t)w * 32 + lane] = make_uint2(l0, l1);
}

// ============================================================================
// Kernel 2: split-bf16 GEMM via mma.sync.m16n8k16 (HMMA tensor path).
// Block: 64 rows x 128 cols, 256 threads (8 warps), warp tile 32x32.
// smem: A hi/lo 16KB each + B hi/lo 32KB each = 96KB -> 2 blocks/SM.
// D = Ahi*Bhi + Ahi*Blo + Alo*Bhi, fp32 accumulate.
// ============================================================================
#define BM 64
#define OFF_AHI 0
#define OFF_ALO 16384
#define OFF_BHI 32768
#define OFF_BLO 65536
#define MMA_SMEM 98304

__global__ void __launch_bounds__(256, 2)
mma_kernel(float* __restrict__ out, int n) {
    extern __shared__ char smem[];
    const unsigned sb = smem_u32(smem);
    const int tid  = threadIdx.x;
    const int wid  = tid >> 5;
    const int lane = tid & 31;
    const int row0 = blockIdx.x * BM;

    // ---- Load A tiles (64 rows x 16 chunks of 16B), swizzled ----
#pragma unroll
    for (int u = tid; u < BM * 16; u += 256) {
        const int row = u >> 4;
        const int c   = u & 15;
        const int gr  = row0 + row;
        uint4 vh = make_uint4(0, 0, 0, 0), vl = vh;
        if (gr < n) {
            vh = g_XpHi4[(size_t)gr * 16 + c];
            vl = g_XpLo4[(size_t)gr * 16 + c];
        }
        const unsigned so = sw_off(row, c);
        STS128(sb + OFF_AHI + so, vh);
        STS128(sb + OFF_ALO + so, vl);
    }
    // ---- Load B tiles (128 n-rows x 16 chunks), swizzled ----
#pragma unroll
    for (int u = tid; u < D * 16; u += 256) {
        const int row = u >> 4;
        const int c   = u & 15;
        const uint4 vh = g_WtHi4[u];
        const uint4 vl = g_WtLo4[u];
        const unsigned so = sw_off(row, c);
        STS128(sb + OFF_BHI + so, vh);
        STS128(sb + OFF_BLO + so, vl);
    }
    __syncthreads();

    // warp tile: rows wm*32 (2 m16 tiles), cols wn*32 (4 n8 tiles)
    const int wm = wid >> 2;  // 0..1
    const int wn = wid & 3;   // 0..3

    float acc[2][4][4];
#pragma unroll
    for (int mt = 0; mt < 2; mt++)
#pragma unroll
        for (int nt = 0; nt < 4; nt++)
#pragma unroll
            for (int i = 0; i < 4; i++) acc[mt][nt][i] = 0.f;

    const int lrow = lane & 15;
    const int lch  = lane >> 4;

#pragma unroll 2
    for (int ks = 0; ks < 8; ks++) {
        const int cb = ks * 2 + lch;

        unsigned ah[2][4], al[2][4];
#pragma unroll
        for (int mt = 0; mt < 2; mt++) {
            const int row = wm * 32 + mt * 16 + lrow;
            const unsigned so = sw_off(row, cb);
            LDSM4(ah[mt][0], ah[mt][1], ah[mt][2], ah[mt][3], sb + OFF_AHI + so);
            LDSM4(al[mt][0], al[mt][1], al[mt][2], al[mt][3], sb + OFF_ALO + so);
        }
        unsigned bh[2][4], bl[2][4];
#pragma unroll
        for (int np = 0; np < 2; np++) {
            const int nrow = wn * 32 + np * 16 + lrow;
            const unsigned so = sw_off(nrow, cb);
            LDSM4(bh[np][0], bh[np][1], bh[np][2], bh[np][3], sb + OFF_BHI + so);
            LDSM4(bl[np][0], bl[np][1], bl[np][2], bl[np][3], sb + OFF_BLO + so);
        }

#pragma unroll
        for (int mt = 0; mt < 2; mt++)
#pragma unroll
            for (int nt = 0; nt < 4; nt++) {
                const int np = nt >> 1, hf = nt & 1;
                MMA16816(acc[mt][nt], ah[mt], bh[np][hf], bh[np][hf + 2]);
                MMA16816(acc[mt][nt], ah[mt], bl[np][hf], bl[np][hf + 2]);
                MMA16816(acc[mt][nt], al[mt], bh[np][hf], bh[np][hf + 2]);
            }
    }

    // ---- Epilogue: c0,c1 -> row lane/4; c2,c3 -> row lane/4 + 8 ----
#pragma unroll
    for (int mt = 0; mt < 2; mt++) {
        const int rg = row0 + wm * 32 + mt * 16 + (lane >> 2);
#pragma unroll
        for (int nt = 0; nt < 4; nt++) {
            const int col = wn * 32 + nt * 8 + (lane & 3) * 2;
            if (rg < n)
                *reinterpret_cast<float2*>(&out[(size_t)rg * D + col]) =
                    make_float2(acc[mt][nt][0], acc[mt][nt][1]);
            if (rg + 8 < n)
                *reinterpret_cast<float2*>(&out[(size_t)(rg + 8) * D + col]) =
                    make_float2(acc[mt][nt][2], acc[mt][nt][3]);
        }
    }
}

extern "C" void kernel_launch(void* const* d_in, const int* in_sizes, int n_in,
                              void* d_out, int out_size) {
    const float* X      = (const float*)d_in[0];
    const float* W      = (const float*)d_in[1];
    const int*   rowptr = (const int*)d_in[2];
    const int*   colidx = (const int*)d_in[3];
    float*       out    = (float*)d_out;

    const int n = in_sizes[2] - 1;  // row_pointers has N+1 entries

    // Kernel 0: W -> transposed bf16 hi/lo
    wconv_kernel<<<(D * D + 255) / 256, 256>>>(W);

    // Kernel 1: aggregation (one warp per row), bf16 split output
    {
        const int grid = (n * 32 + 255) / 256;
        agg_kernel<<<grid, 256>>>((const float4*)X, rowptr, colidx, n);
    }

    // Kernel 2: HMMA GEMM
    {
        cudaFuncSetAttribute(mma_kernel,
                             cudaFuncAttributeMaxDynamicSharedMemorySize,
                             MMA_SMEM);
        const int grid = (n + BM - 1) / BM;
        mma_kernel<<<grid, 256, MMA_SMEM>>>(out, n);
    }
}